// round 15
// baseline (speedup 1.0000x reference)
#include <cuda_runtime.h>

#define THREADS 64   // one row (1024-pt FFT) per CTA: 2 warps, 32 lane-pairs

// ===================== compile-time twiddle table =======================
// TW[k*32 + n] = exp(-2*pi*i * n*k / 1024). Runtime reads rows k=h, 2, 16.
__host__ __device__ constexpr double tsin_(double x) {
    double t = x, s = x;
    for (int k = 1; k < 13; k++) { t *= -x * x / ((2.0 * k) * (2.0 * k + 1.0)); s += t; }
    return s;
}
__host__ __device__ constexpr double tcos_(double x) {
    double t = 1.0, s = 1.0;
    for (int k = 1; k < 13; k++) { t *= -x * x / ((2.0 * k - 1.0) * (2.0 * k)); s += t; }
    return s;
}
struct alignas(16) TwTab { float2 v[1024]; };
__host__ __device__ constexpr TwTab make_tw_() {
    TwTab t{};
    constexpr double PI = 3.14159265358979323846;
    for (int k = 0; k < 32; k++)
        for (int n = 0; n < 32; n++) {
            double ang = -2.0 * PI * (double)(n * k) / 1024.0;
            if (ang < -PI) ang += 2.0 * PI;
            t.v[k * 32 + n] = float2{ (float)tcos_(ang), (float)tsin_(ang) };
        }
    return t;
}
__device__ const TwTab TW = make_tw_();

__device__ __forceinline__ float2 cmulf(float2 a, float2 b) {
    return make_float2(fmaf(a.x, b.x, -a.y * b.y), fmaf(a.x, b.y, a.y * b.x));
}

// 16-point radix-4 DIF FFT (2 stages). Natural input; reg j holds X[dr4(j)],
// dr4(j) = ((j&3)<<2) | (j>>2).
__device__ __forceinline__ void fft16(float* ar, float* ai)
{
    constexpr float Cq = 0.92387953251128674f;
    constexpr float Sq = 0.38268343236508977f;
    constexpr float Rh = 0.70710678118654752f;
    constexpr float AR[4] = {1.f,  Cq,  Rh,  Sq}, AI[4] = {0.f, -Sq, -Rh, -Cq};
    constexpr float BR[4] = {1.f,  Rh, 0.f, -Rh}, BI[4] = {0.f, -Rh, -1.f, -Rh};
    constexpr float CR[4] = {1.f,  Sq, -Rh, -Cq}, CI[4] = {0.f, -Cq, -Rh,  Sq};

#pragma unroll
    for (int j = 0; j < 4; j++) {
        float t0r = ar[j]   + ar[j+8],  t0i = ai[j]   + ai[j+8];
        float t1r = ar[j]   - ar[j+8],  t1i = ai[j]   - ai[j+8];
        float t2r = ar[j+4] + ar[j+12], t2i = ai[j+4] + ai[j+12];
        float t3r = ai[j+4] - ai[j+12], t3i = ar[j+12] - ar[j+4];
        ar[j] = t0r + t2r;  ai[j] = t0i + t2i;
        float u1r = t1r + t3r, u1i = t1i + t3i;
        float u2r = t0r - t2r, u2i = t0i - t2i;
        float u3r = t1r - t3r, u3i = t1i - t3i;
        ar[j+4]  = u1r*AR[j] - u1i*AI[j];  ai[j+4]  = u1r*AI[j] + u1i*AR[j];
        ar[j+8]  = u2r*BR[j] - u2i*BI[j];  ai[j+8]  = u2r*BI[j] + u2i*BR[j];
        ar[j+12] = u3r*CR[j] - u3i*CI[j];  ai[j+12] = u3r*CI[j] + u3i*CR[j];
    }
#pragma unroll
    for (int g = 0; g < 4; g++) {
        const int b = 4 * g;
        float t0r = ar[b]   + ar[b+2], t0i = ai[b]   + ai[b+2];
        float t1r = ar[b]   - ar[b+2], t1i = ai[b]   - ai[b+2];
        float t2r = ar[b+1] + ar[b+3], t2i = ai[b+1] + ai[b+3];
        float t3r = ai[b+1] - ai[b+3], t3i = ar[b+3] - ar[b+1];
        ar[b]   = t0r + t2r;  ai[b]   = t0i + t2i;
        ar[b+1] = t1r + t3r;  ai[b+1] = t1i + t3i;
        ar[b+2] = t0r - t2r;  ai[b+2] = t0i - t2i;
        ar[b+3] = t1r - t3r;  ai[b+3] = t1i - t3i;
    }
}

__device__ __forceinline__ int dr4(int j) { return ((j & 3) << 2) | (j >> 2); }

// DIF lane-pair split before fft16. Lane h=0 holds x[j], lane h=1 holds
// x[j+16]. After split + fft16: lane h, reg j => X32[2*dr4(j) + h].
__device__ __forceinline__ void dif_split32(float* ar, float* ai, int h)
{
    constexpr float WC[16] = { 1.0f, 0.98078528040323044f, 0.92387953251128674f,
        0.83146961230254524f, 0.70710678118654752f, 0.55557023301960222f,
        0.38268343236508977f, 0.19509032201612827f, 0.0f, -0.19509032201612827f,
       -0.38268343236508977f, -0.55557023301960222f, -0.70710678118654752f,
       -0.83146961230254524f, -0.92387953251128674f, -0.98078528040323044f };
    constexpr float WS[16] = { 0.0f, -0.19509032201612827f, -0.38268343236508977f,
       -0.55557023301960222f, -0.70710678118654752f, -0.83146961230254524f,
       -0.92387953251128674f, -0.98078528040323044f, -1.0f, -0.98078528040323044f,
       -0.92387953251128674f, -0.83146961230254524f, -0.70710678118654752f,
       -0.55557023301960222f, -0.38268343236508977f, -0.19509032201612827f };

#pragma unroll
    for (int j = 0; j < 16; j++) {
        float br = __shfl_xor_sync(0xffffffffu, ar[j], 16);
        float bi = __shfl_xor_sync(0xffffffffu, ai[j], 16);
        if (h) {
            float dr = br - ar[j], di = bi - ai[j];
            ar[j] = dr * WC[j] - di * WS[j];
            ai[j] = dr * WS[j] + di * WC[j];
        } else {
            ar[j] += br;
            ai[j] += bi;
        }
    }
}

// Four-step 1024 = 32 x 32, one row per 64-thread CTA. 53-reg / 19-CTA
// probe of the occupancy-vs-MLP curve (55/18 = 40.32us, 48/20 = 43.0us).
// Inter-phase twiddles from three L2-hot table bases (Q = W^(h*n1),
// V = W^(2*n1), V8 = W^(16*n1)) via two parallel 7-deep product chains.
__global__ void __launch_bounds__(THREADS, 19) fft1024_kernel(
    const float* __restrict__ xin, float* __restrict__ xout)
{
    __shared__ __align__(16) float2 sz[32 * 34];

    const int tid = threadIdx.x;     // 0..63
    const int w = tid >> 5;          // warp
    const int l = tid & 31;
    const int h = l >> 4;            // lane-pair half
    const int q = l & 15;
    const int n1 = w * 16 + q;       // column (phase A) / row (phase B)

    // twiddle bases, issued first (independent of data)
    const float2 Q  = TW.v[h * 32 + n1];    // W1024^(h*n1)
    const float2 V  = TW.v[64 + n1];        // W1024^(2*n1)
    const float2 V8 = TW.v[512 + n1];       // W1024^(16*n1) = V^8

    const float2* __restrict__ xb =
        reinterpret_cast<const float2*>(xin) + (size_t)blockIdx.x * 1024;
    float2* __restrict__ yb =
        reinterpret_cast<float2*>(xout) + (size_t)blockIdx.x * 1024;

    float ar[16], ai[16];

    // ===== Phase A: 32-pt FFT over n2, column n1 ===========================
#pragma unroll
    for (int j = 0; j < 16; j++) {
        float2 v = __ldcs(&xb[(h * 16 + j) * 32 + n1]);
        ar[j] = v.x;
        ai[j] = v.y;
    }
    dif_split32(ar, ai, h);
    fft16(ar, ai);          // lane h, reg j -> Y[n1][k1], k1 = 2*dr4(j)+h

    // inter-phase twiddle W1024^(n1*k1) = Q * V^m (k1 = 2m+h), two parallel
    // 7-deep chains; transposed store sz[k1][n1].
    {
        float2 Pa = Q;                      // Q * V^0
        float2 Pb = cmulf(Q, V8);           // Q * V^8
#pragma unroll
        for (int m = 0; m < 8; m++) {
            const int ja = dr4(m);          // reg holding k1 = 2m+h
            const int jb = dr4(m + 8);      // reg holding k1 = 2(m+8)+h
            sz[(2 * m + h) * 34 + n1] =
                cmulf(make_float2(ar[ja], ai[ja]), Pa);
            sz[(2 * (m + 8) + h) * 34 + n1] =
                cmulf(make_float2(ar[jb], ai[jb]), Pb);
            if (m < 7) {
                Pa = cmulf(Pa, V);
                Pb = cmulf(Pb, V);
            }
        }
    }
    __syncthreads();

    // ===== Phase B: 32-pt FFT over k1 within row n1 ========================
    // lane h reads contiguous elements h*16..h*16+15 of row n1 -> 8 x LDS.128
    {
        const float4* lp4 = reinterpret_cast<const float4*>(&sz[n1 * 34 + h * 16]);
#pragma unroll
        for (int i = 0; i < 8; i++) {
            float4 v = lp4[i];
            ar[2 * i]     = v.x;  ai[2 * i]     = v.y;
            ar[2 * i + 1] = v.z;  ai[2 * i + 1] = v.w;
        }
    }
    dif_split32(ar, ai, h);
    fft16(ar, ai);          // lane h, reg j -> X[n1 + 32*k2], k2 = 2*dr4(j)+h

#pragma unroll
    for (int j = 0; j < 16; j++) {
        const int k2 = 2 * dr4(j) + h;
        __stcs(&yb[n1 + 32 * k2], make_float2(ar[j], ai[j]));
    }
}

extern "C" void kernel_launch(void* const* d_in, const int* in_sizes, int n_in,
                              void* d_out, int out_size)
{
    const float* x = (const float*)d_in[0];
    float* y = (float*)d_out;
    const int B = in_sizes[0] / 2048;   // 1024 complex per row
    fft1024_kernel<<<B, THREADS>>>(x, y);
}

// round 16
// speedup vs baseline: 1.0530x; 1.0530x over previous
#include <cuda_runtime.h>

#define THREADS 64   // one row (1024-pt FFT) per CTA: 2 warps, 32 lane-pairs

// ===================== compile-time twiddle table =======================
// TW[k*32 + n] = exp(-2*pi*i * n*k / 1024). Runtime reads rows k=h, 2, 16.
__host__ __device__ constexpr double tsin_(double x) {
    double t = x, s = x;
    for (int k = 1; k < 13; k++) { t *= -x * x / ((2.0 * k) * (2.0 * k + 1.0)); s += t; }
    return s;
}
__host__ __device__ constexpr double tcos_(double x) {
    double t = 1.0, s = 1.0;
    for (int k = 1; k < 13; k++) { t *= -x * x / ((2.0 * k - 1.0) * (2.0 * k)); s += t; }
    return s;
}
struct alignas(16) TwTab { float2 v[1024]; };
__host__ __device__ constexpr TwTab make_tw_() {
    TwTab t{};
    constexpr double PI = 3.14159265358979323846;
    for (int k = 0; k < 32; k++)
        for (int n = 0; n < 32; n++) {
            double ang = -2.0 * PI * (double)(n * k) / 1024.0;
            if (ang < -PI) ang += 2.0 * PI;
            t.v[k * 32 + n] = float2{ (float)tcos_(ang), (float)tsin_(ang) };
        }
    return t;
}
__device__ const TwTab TW = make_tw_();

__device__ __forceinline__ float2 cmulf(float2 a, float2 b) {
    return make_float2(fmaf(a.x, b.x, -a.y * b.y), fmaf(a.x, b.y, a.y * b.x));
}

// 16-point radix-4 DIF FFT (2 stages). Natural input; reg j holds X[dr4(j)],
// dr4(j) = ((j&3)<<2) | (j>>2).
__device__ __forceinline__ void fft16(float* ar, float* ai)
{
    constexpr float Cq = 0.92387953251128674f;
    constexpr float Sq = 0.38268343236508977f;
    constexpr float Rh = 0.70710678118654752f;
    constexpr float AR[4] = {1.f,  Cq,  Rh,  Sq}, AI[4] = {0.f, -Sq, -Rh, -Cq};
    constexpr float BR[4] = {1.f,  Rh, 0.f, -Rh}, BI[4] = {0.f, -Rh, -1.f, -Rh};
    constexpr float CR[4] = {1.f,  Sq, -Rh, -Cq}, CI[4] = {0.f, -Cq, -Rh,  Sq};

#pragma unroll
    for (int j = 0; j < 4; j++) {
        float t0r = ar[j]   + ar[j+8],  t0i = ai[j]   + ai[j+8];
        float t1r = ar[j]   - ar[j+8],  t1i = ai[j]   - ai[j+8];
        float t2r = ar[j+4] + ar[j+12], t2i = ai[j+4] + ai[j+12];
        float t3r = ai[j+4] - ai[j+12], t3i = ar[j+12] - ar[j+4];
        ar[j] = t0r + t2r;  ai[j] = t0i + t2i;
        float u1r = t1r + t3r, u1i = t1i + t3i;
        float u2r = t0r - t2r, u2i = t0i - t2i;
        float u3r = t1r - t3r, u3i = t1i - t3i;
        ar[j+4]  = u1r*AR[j] - u1i*AI[j];  ai[j+4]  = u1r*AI[j] + u1i*AR[j];
        ar[j+8]  = u2r*BR[j] - u2i*BI[j];  ai[j+8]  = u2r*BI[j] + u2i*BR[j];
        ar[j+12] = u3r*CR[j] - u3i*CI[j];  ai[j+12] = u3r*CI[j] + u3i*CR[j];
    }
#pragma unroll
    for (int g = 0; g < 4; g++) {
        const int b = 4 * g;
        float t0r = ar[b]   + ar[b+2], t0i = ai[b]   + ai[b+2];
        float t1r = ar[b]   - ar[b+2], t1i = ai[b]   - ai[b+2];
        float t2r = ar[b+1] + ar[b+3], t2i = ai[b+1] + ai[b+3];
        float t3r = ai[b+1] - ai[b+3], t3i = ar[b+3] - ar[b+1];
        ar[b]   = t0r + t2r;  ai[b]   = t0i + t2i;
        ar[b+1] = t1r + t3r;  ai[b+1] = t1i + t3i;
        ar[b+2] = t0r - t2r;  ai[b+2] = t0i - t2i;
        ar[b+3] = t1r - t3r;  ai[b+3] = t1i - t3i;
    }
}

__device__ __forceinline__ int dr4(int j) { return ((j & 3) << 2) | (j >> 2); }

// DIF lane-pair split before fft16. Lane h=0 holds x[j], lane h=1 holds
// x[j+16]. After split + fft16: lane h, reg j => X32[2*dr4(j) + h].
__device__ __forceinline__ void dif_split32(float* ar, float* ai, int h)
{
    constexpr float WC[16] = { 1.0f, 0.98078528040323044f, 0.92387953251128674f,
        0.83146961230254524f, 0.70710678118654752f, 0.55557023301960222f,
        0.38268343236508977f, 0.19509032201612827f, 0.0f, -0.19509032201612827f,
       -0.38268343236508977f, -0.55557023301960222f, -0.70710678118654752f,
       -0.83146961230254524f, -0.92387953251128674f, -0.98078528040323044f };
    constexpr float WS[16] = { 0.0f, -0.19509032201612827f, -0.38268343236508977f,
       -0.55557023301960222f, -0.70710678118654752f, -0.83146961230254524f,
       -0.92387953251128674f, -0.98078528040323044f, -1.0f, -0.98078528040323044f,
       -0.92387953251128674f, -0.83146961230254524f, -0.70710678118654752f,
       -0.55557023301960222f, -0.38268343236508977f, -0.19509032201612827f };

#pragma unroll
    for (int j = 0; j < 16; j++) {
        float br = __shfl_xor_sync(0xffffffffu, ar[j], 16);
        float bi = __shfl_xor_sync(0xffffffffu, ai[j], 16);
        if (h) {
            float dr = br - ar[j], di = bi - ai[j];
            ar[j] = dr * WC[j] - di * WS[j];
            ai[j] = dr * WS[j] + di * WC[j];
        } else {
            ar[j] += br;
            ai[j] += bi;
        }
    }
}

// Four-step 1024 = 32 x 32, one row per 64-thread CTA. 56-reg / 18-CTA
// operating point (measured optimum across the 48..64-reg sweep).
// Inter-phase twiddles from three L2-hot table bases (Q = W^(h*n1),
// V = W^(2*n1), V8 = W^(16*n1)) via two parallel 7-deep product chains.
__global__ void __launch_bounds__(THREADS, 18) fft1024_kernel(
    const float* __restrict__ xin, float* __restrict__ xout)
{
    __shared__ __align__(16) float2 sz[32 * 34];

    const int tid = threadIdx.x;     // 0..63
    const int w = tid >> 5;          // warp
    const int l = tid & 31;
    const int h = l >> 4;            // lane-pair half
    const int q = l & 15;
    const int n1 = w * 16 + q;       // column (phase A) / row (phase B)

    // twiddle bases, issued first (independent of data)
    const float2 Q  = TW.v[h * 32 + n1];    // W1024^(h*n1)
    const float2 V  = TW.v[64 + n1];        // W1024^(2*n1)
    const float2 V8 = TW.v[512 + n1];       // W1024^(16*n1) = V^8

    const float2* __restrict__ xb =
        reinterpret_cast<const float2*>(xin) + (size_t)blockIdx.x * 1024;
    float2* __restrict__ yb =
        reinterpret_cast<float2*>(xout) + (size_t)blockIdx.x * 1024;

    float ar[16], ai[16];

    // ===== Phase A: 32-pt FFT over n2, column n1 ===========================
#pragma unroll
    for (int j = 0; j < 16; j++) {
        float2 v = __ldcs(&xb[(h * 16 + j) * 32 + n1]);
        ar[j] = v.x;
        ai[j] = v.y;
    }
    dif_split32(ar, ai, h);
    fft16(ar, ai);          // lane h, reg j -> Y[n1][k1], k1 = 2*dr4(j)+h

    // inter-phase twiddle W1024^(n1*k1) = Q * V^m (k1 = 2m+h), two parallel
    // 7-deep chains; transposed store sz[k1][n1].
    {
        float2 Pa = Q;                      // Q * V^0
        float2 Pb = cmulf(Q, V8);           // Q * V^8
#pragma unroll
        for (int m = 0; m < 8; m++) {
            const int ja = dr4(m);          // reg holding k1 = 2m+h
            const int jb = dr4(m + 8);      // reg holding k1 = 2(m+8)+h
            sz[(2 * m + h) * 34 + n1] =
                cmulf(make_float2(ar[ja], ai[ja]), Pa);
            sz[(2 * (m + 8) + h) * 34 + n1] =
                cmulf(make_float2(ar[jb], ai[jb]), Pb);
            if (m < 7) {
                Pa = cmulf(Pa, V);
                Pb = cmulf(Pb, V);
            }
        }
    }
    __syncthreads();

    // ===== Phase B: 32-pt FFT over k1 within row n1 ========================
    // lane h reads contiguous elements h*16..h*16+15 of row n1 -> 8 x LDS.128
    {
        const float4* lp4 = reinterpret_cast<const float4*>(&sz[n1 * 34 + h * 16]);
#pragma unroll
        for (int i = 0; i < 8; i++) {
            float4 v = lp4[i];
            ar[2 * i]     = v.x;  ai[2 * i]     = v.y;
            ar[2 * i + 1] = v.z;  ai[2 * i + 1] = v.w;
        }
    }
    dif_split32(ar, ai, h);
    fft16(ar, ai);          // lane h, reg j -> X[n1 + 32*k2], k2 = 2*dr4(j)+h

#pragma unroll
    for (int j = 0; j < 16; j++) {
        const int k2 = 2 * dr4(j) + h;
        __stcs(&yb[n1 + 32 * k2], make_float2(ar[j], ai[j]));
    }
}

extern "C" void kernel_launch(void* const* d_in, const int* in_sizes, int n_in,
                              void* d_out, int out_size)
{
    const float* x = (const float*)d_in[0];
    float* y = (float*)d_out;
    const int B = in_sizes[0] / 2048;   // 1024 complex per row
    fft1024_kernel<<<B, THREADS>>>(x, y);
}